// round 17
// baseline (speedup 1.0000x reference)
#include <cuda_runtime.h>
#include <cstdint>

// Problem shape (fixed): x:(32,512,64,64) f32, weight:(1,1,3,3), k=256
#define BB 32
#define NN 512
#define HH 64
#define WW 64
#define IMG_ELEMS (HH * WW)          // 4096
#define IMG_BYTES (IMG_ELEMS * 4)    // 16384

// Scratch (no cudaMalloc allowed)
__device__ float2 g_scores[BB * NN];

// ---------------------------------------------------------------------------
// Phase 1 (champion R4/R6 codegen — body untouched): warp-per-image conv
// score. Lane li owns cols 2li,2li+1. Rows in chunks of 8: all 8 LDG.64
// issued before compute (MLP=8). Trailing PDL trigger.
// grid = B*N/8, block = 256 (8 warps = 8 images).
// ---------------------------------------------------------------------------
__global__ __launch_bounds__(256) void score_kernel(
    const float* __restrict__ x, const float* __restrict__ w,
    float2* __restrict__ scores)
{
    const int li   = threadIdx.x & 31;
    const int img  = blockIdx.x * 8 + (threadIdx.x >> 5);
    const bool tail = (li == 31);                 // cols 62,63: invalid outputs

    const float wc = w[0];   // corners
    const float wE = w[1];   // edges
    const float wm = w[4];   // center

    const float2* b2 = reinterpret_cast<const float2*>(
        x + (size_t)img * IMG_ELEMS) + li;        // 32 float2 per row

    float Ha1[2], Hm1[2], Ha2[2], Hm2[2];
    float s = 0.f, e = 0.f;

    float2 v[8];

#pragma unroll
    for (int i = 0; i < 8; i++) v[i] = b2[i * 32];

    {
        float nx = __shfl_down_sync(0xffffffffu, v[0].x, 1);
        float ny = __shfl_down_sync(0xffffffffu, v[0].y, 1);
        Ha2[0] = v[0].x + nx;  Hm2[0] = v[0].y;
        Ha2[1] = v[0].y + ny;  Hm2[1] = nx;
        nx = __shfl_down_sync(0xffffffffu, v[1].x, 1);
        ny = __shfl_down_sync(0xffffffffu, v[1].y, 1);
        Ha1[0] = v[1].x + nx;  Hm1[0] = v[1].y;
        Ha1[1] = v[1].y + ny;  Hm1[1] = nx;
    }

#define DO_ROW(vv)                                                          \
    {                                                                       \
        float nx = __shfl_down_sync(0xffffffffu, (vv).x, 1);                \
        float ny = __shfl_down_sync(0xffffffffu, (vv).y, 1);                \
        float Hac0 = (vv).x + nx, Hmc0 = (vv).y;                            \
        float Hac1 = (vv).y + ny, Hmc1 = nx;                                \
        float s1a = Ha2[0] + Hac0;                                          \
        float s2a = (Hm2[0] + Hmc0) + Ha1[0];                               \
        float vra = fmaf(wc, s1a, fmaf(wE, s2a, wm * Hm1[0]));              \
        float s1b = Ha2[1] + Hac1;                                          \
        float s2b = (Hm2[1] + Hmc1) + Ha1[1];                               \
        float vrb = fmaf(wc, s1b, fmaf(wE, s2b, wm * Hm1[1]));              \
        float row = fabsf(vra) + fabsf(vrb);                                \
        if (tail) row = 0.f;                                                \
        float tt  = __fadd_rn(s, row);                                      \
        e = __fadd_rn(e, __fadd_rn(__fsub_rn(s, tt), row));                 \
        s = tt;                                                             \
        Ha2[0] = Ha1[0]; Hm2[0] = Hm1[0]; Ha1[0] = Hac0; Hm1[0] = Hmc0;     \
        Ha2[1] = Ha1[1]; Hm2[1] = Hm1[1]; Ha1[1] = Hac1; Hm1[1] = Hmc1;     \
    }

#pragma unroll
    for (int i = 2; i < 8; i++) DO_ROW(v[i]);

    for (int c = 1; c < 8; c++) {
#pragma unroll
        for (int i = 0; i < 8; i++) v[i] = b2[(c * 8 + i) * 32];
#pragma unroll
        for (int i = 0; i < 8; i++) DO_ROW(v[i]);
    }
#undef DO_ROW

#pragma unroll
    for (int off = 16; off; off >>= 1) {
        float s2 = __shfl_down_sync(0xffffffffu, s, off);
        float e2 = __shfl_down_sync(0xffffffffu, e, off);
        float tt  = __fadd_rn(s, s2);
        float z   = __fsub_rn(tt, s);
        float err = __fadd_rn(__fsub_rn(s, __fsub_rn(tt, z)), __fsub_rn(s2, z));
        e = __fadd_rn(__fadd_rn(e, e2), err);
        s = tt;
    }

    if (li == 0) {
        float h = __fadd_rn(s, e);
        float l = __fadd_rn(__fsub_rn(s, h), e);
        scores[img] = make_float2(h, l);
    }

    // PDL trigger: this CTA's work (incl. the score store) is done.
    asm volatile("griddepcontrol.launch_dependents;" ::: "memory");
}

// ---------------------------------------------------------------------------
// Phase 2+3 fused (PDL secondary, runs serial after score): 256 blocks x
// 128 threads, 8 blocks per batch. Each block ranks its batch's 512 u64
// sortable keys (4 candidates/thread), extracts its 32-image rank slice,
// then thread 0 drives the proven GS=6/GD=4 bulk-copy ring (96KB, 2/SM).
// The key array aliases ring stage 0 (read-complete before first load lands).
// ---------------------------------------------------------------------------
#define GS 6          // ring stages
#define GD 4          // prefetch depth (<= GS-2 for WAR safety)

__device__ __forceinline__ uint32_t f2u_sortable(float f) {
    uint32_t u = __float_as_uint(f);
    return u ^ ((u & 0x80000000u) ? 0xFFFFFFFFu : 0x80000000u);
}

__device__ __forceinline__ void mbar_wait(uint32_t mbar, uint32_t parity) {
    uint32_t done;
    do {
        asm volatile(
            "{\n\t.reg .pred p;\n\t"
            "mbarrier.try_wait.parity.shared.b64 p, [%1], %2;\n\t"
            "selp.b32 %0, 1, 0, p;\n\t}"
            : "=r"(done) : "r"(mbar), "r"(parity) : "memory");
    } while (!done);
}

__device__ __forceinline__ void bulk_load(uint32_t dst_smem, const void* src,
                                          uint32_t mbar) {
    asm volatile(
        "mbarrier.arrive.expect_tx.shared.b64 _, [%0], %1;"
        :: "r"(mbar), "r"((uint32_t)IMG_BYTES) : "memory");
    asm volatile(
        "cp.async.bulk.shared::cluster.global.mbarrier::complete_tx::bytes "
        "[%0], [%1], %2, [%3];"
        :: "r"(dst_smem), "l"(src), "r"((uint32_t)IMG_BYTES), "r"(mbar)
        : "memory");
}

__global__ __launch_bounds__(128) void topk_gather_kernel(
    const float* __restrict__ x, const float2* __restrict__ scores,
    float* __restrict__ out, int k)
{
    extern __shared__ __align__(128) char dsm[];      // GS*16KB ring
    __shared__ int slice[64];                          // rank-slice indices
    __shared__ __align__(8) unsigned long long mbars[GS];

    // keys alias ring stage 0 (4KB of 16KB); consumed before first TMA write
    unsigned long long* sk = reinterpret_cast<unsigned long long*>(dsm);

    const int tid   = threadIdx.x;
    const int batch = blockIdx.x >> 3;
    const int isl   = k >> 3;                          // 32 images per block
    const int r0    = (blockIdx.x & 7) * isl;

    asm volatile("griddepcontrol.wait;" ::: "memory"); // score grid done

    // ---- build sortable keys ----
    for (int i = tid; i < NN; i += 128) {
        float2 f = scores[batch * NN + i];
        sk[i] = ((unsigned long long)f2u_sortable(f.x) << 32) |
                f2u_sortable(f.y);
    }
    __syncthreads();

    // ---- rank 4 candidates per thread ----
    unsigned long long kreg[4];
    int rank[4] = {0, 0, 0, 0};
#pragma unroll
    for (int c = 0; c < 4; c++) kreg[c] = sk[tid + c * 128];

#pragma unroll 4
    for (int m = 0; m < NN; m++) {
        const unsigned long long o = sk[m];
#pragma unroll
        for (int c = 0; c < 4; c++)
            rank[c] += (o > kreg[c]) ||
                       (o == kreg[c] && m < tid + c * 128);
    }
#pragma unroll
    for (int c = 0; c < 4; c++) {
        const int r = rank[c];
        if (r >= r0 && r < r0 + isl) slice[r - r0] = tid + c * 128;
    }
    __syncthreads();                                   // slice complete; sk dead

    if (tid != 0) return;                              // thread 0 drives copies

    const uint32_t buf0  = (uint32_t)__cvta_generic_to_shared(dsm);
    const uint32_t mbar0 = (uint32_t)__cvta_generic_to_shared(mbars);

#pragma unroll
    for (int st = 0; st < GS; st++)
        asm volatile("mbarrier.init.shared.b64 [%0], 1;"
                     :: "r"(mbar0 + st * 8) : "memory");
    asm volatile("fence.proxy.async.shared::cta;" ::: "memory");

    const size_t xrow  = (size_t)batch * NN;
    const size_t obase = (size_t)batch * k + r0;

    // prologue: GD loads in flight
#pragma unroll
    for (int j = 0; j < GD; j++)
        bulk_load(buf0 + (j % GS) * IMG_BYTES,
                  x + (xrow + slice[j]) * IMG_ELEMS,
                  mbar0 + (j % GS) * 8);

    for (int j = 0; j < isl; j++) {
        const int st = j % GS;
        mbar_wait(mbar0 + st * 8, (j / GS) & 1);

        const float* dst = out + (obase + j) * IMG_ELEMS;
        asm volatile(
            "cp.async.bulk.global.shared::cta.bulk_group [%0], [%1], %2;"
            :: "l"(dst), "r"(buf0 + st * IMG_BYTES), "r"((uint32_t)IMG_BYTES)
            : "memory");
        asm volatile("cp.async.bulk.commit_group;" ::: "memory");

        const int jn = j + GD;
        if (jn < isl) {
            // stage jn%GS last stored at iter jn-GS <= j-2; committed = j+1,
            // pending <= GS-GD => that store's smem read is complete.
            asm volatile("cp.async.bulk.wait_group.read %0;"
                         :: "n"(GS - GD) : "memory");
            bulk_load(buf0 + (jn % GS) * IMG_BYTES,
                      x + (xrow + slice[jn]) * IMG_ELEMS,
                      mbar0 + (jn % GS) * 8);
        }
    }
    asm volatile("cp.async.bulk.wait_group 0;" ::: "memory");
}

// ---------------------------------------------------------------------------
extern "C" void kernel_launch(void* const* d_in, const int* in_sizes, int n_in,
                              void* d_out, int out_size)
{
    const float* x = (const float*)d_in[0];
    const float* w = (const float*)d_in[1];
    float* out = (float*)d_out;

    const int k = out_size / (BB * IMG_ELEMS);   // = 256

    const int gather_smem = GS * IMG_BYTES;      // 98304 B dynamic
    static int attr_set = 0;
    if (!attr_set) {
        cudaFuncSetAttribute(topk_gather_kernel,
                             cudaFuncAttributeMaxDynamicSharedMemorySize,
                             gather_smem);
        attr_set = 1;
    }

    // node 1: score (ends with launch_dependents)
    score_kernel<<<(BB * NN) / 8, 256>>>(x, w, g_scores);

    // node 2: fused topk+gather with programmatic dependent launch on score
    {
        cudaLaunchAttribute at[1];
        at[0].id = cudaLaunchAttributeProgrammaticStreamSerialization;
        at[0].val.programmaticStreamSerializationAllowed = 1;
        cudaLaunchConfig_t cfg = {};
        cfg.gridDim          = dim3(BB * 8, 1, 1);
        cfg.blockDim         = dim3(128, 1, 1);
        cfg.dynamicSmemBytes = gather_smem;
        cfg.attrs            = at;
        cfg.numAttrs         = 1;
        float2* sc = g_scores;
        cudaLaunchKernelEx(&cfg, topk_gather_kernel,
                           x, (const float2*)sc, out, k);
    }
}